// round 11
// baseline (speedup 1.0000x reference)
#include <cuda_runtime.h>
#include <cooperative_groups.h>
#include <math.h>

namespace cg = cooperative_groups;

#define ROW_LEN   65536
#define CSIZE     8
#define SEG       (ROW_LEN / CSIZE)     // 8192 elements per CTA
#define THREADS   512
#define TPT       16                    // thread owns [e0, e0+16)
#define NW        (THREADS / 32)        // 16 warps

#define TREND_SCALING       0.6f
#define DETAIL_PRESERVATION 0.85f
#define SPIKE_THRESHOLD     3.5f
#define SPIKE_DAMPING       0.35f
#define EPS_STD             1e-6f
#define F_KEEP   DETAIL_PRESERVATION                      // 0.85
#define F_DAMP   (DETAIL_PRESERVATION * SPIKE_DAMPING)    // 0.2975
#define C5       ((1.0f - TREND_SCALING) * 0.2f)          // 0.08
#define C11      (TREND_SCALING / 11.0f)

// smem layout (floats) — halo mailboxes + reduction scratch only (~1KB)
#define OFF_AF    0                 // A_first[NW][5]: lane0's r[0..4]
#define OFF_AL    (NW * 5)          // A_last [NW][5]: lane31's r[11..15]
#define OFF_HCL   (2 * NW * 5)      // 160: cross-CTA left r-halo e[-5..-1]
#define OFF_HCR   (OFF_HCL + 5)     // 165: cross-CTA right r-halo e[SEG..SEG+4]
#define OFF_RED   172               // 33 floats: warp partials (s, ss) + thr
#define OFF_MAIL  (OFF_RED + 33)    // 16 floats: per-rank (s, ss)
#define SMEM_FLOATS (OFF_MAIL + 16)
#define SMEM_BYTES  (SMEM_FLOATS * 4)

// reflect over the full row [0, ROW_LEN)
__device__ __forceinline__ int rrow(int g) {
    if (g < 0) g = -g;
    if (g >= ROW_LEN) g = 2 * ROW_LEN - 2 - g;
    return g;
}

// cluster-wide threshold from per-thread (s, ss); deterministic order.
__device__ __forceinline__ float cluster_threshold(
    cg::cluster_group& cl, float s, float ss, float* sm, int rank, int tid)
{
    float* red  = sm + OFF_RED;
    float* mail = sm + OFF_MAIL;
    const unsigned m = 0xffffffffu;
    #pragma unroll
    for (int off = 16; off; off >>= 1) {
        s  += __shfl_down_sync(m, s,  off);
        ss += __shfl_down_sync(m, ss, off);
    }
    const int wid = tid >> 5, lid = tid & 31;
    if (lid == 0) { red[wid] = s; red[NW + wid] = ss; }
    __syncthreads();
    if (tid == 0) {
        float bs = 0.f, bss = 0.f;
        #pragma unroll
        for (int w = 0; w < NW; w++) { bs += red[w]; bss += red[NW + w]; }
        #pragma unroll
        for (int r2 = 0; r2 < CSIZE; r2++) {
            float* pm = cl.map_shared_rank(sm, r2) + OFF_MAIL;
            pm[2 * rank]     = bs;
            pm[2 * rank + 1] = bss;
        }
    }
    cl.sync();
    if (tid == 0) {
        float cs = 0.f, css = 0.f;
        #pragma unroll
        for (int r2 = 0; r2 < CSIZE; r2++) {
            cs  += mail[2 * r2];
            css += mail[2 * r2 + 1];
        }
        const float n = (float)ROW_LEN;
        float var = (css - cs * cs / n) / (n - 1.0f);
        var = fmaxf(var, 0.0f);
        red[2 * NW] = fmaxf(sqrtf(var), EPS_STD) * SPIKE_THRESHOLD;
    }
    __syncthreads();
    return red[2 * NW];
}

__global__ void __launch_bounds__(THREADS, 2) __cluster_dims__(CSIZE, 1, 1)
fd11_kernel(const float* __restrict__ x, float* __restrict__ out)
{
    extern __shared__ float sm[];
    cg::cluster_group cl = cg::this_cluster();
    const int rank = (int)cl.block_rank();
    const int row  = blockIdx.x / CSIZE;
    const int tid  = threadIdx.x;
    const int lane = tid & 31;
    const int w    = tid >> 5;
    const float* xr = x + (size_t)row * ROW_LEN;
    const int e0   = rank * SEG + tid * TPT;   // row-local element 0 of thread
    const unsigned FULL = 0xffffffffu;

    // ===== load x once into registers ========================================
    float v[TPT];
    #pragma unroll
    for (int i = 0; i < TPT / 4; i++) {
        float4 t = *reinterpret_cast<const float4*>(xr + e0 + 4 * i);
        v[4*i+0] = t.x; v[4*i+1] = t.y; v[4*i+2] = t.z; v[4*i+3] = t.w;
    }

    // x halos (±5) via lane shuffles; warp-edge lanes read global + reflect
    float hl[5], hr[5];
    #pragma unroll
    for (int k = 0; k < 5; k++) {
        hl[k] = __shfl_up_sync(FULL, v[11 + k], 1);   // elem e0-5+k
        hr[k] = __shfl_down_sync(FULL, v[k], 1);      // elem e0+16+k
    }
    if (lane == 0) {
        #pragma unroll
        for (int k = 0; k < 5; k++) hl[k] = xr[rrow(e0 - 5 + k)];
    }
    if (lane == 31) {
        #pragma unroll
        for (int k = 0; k < 5; k++) hr[k] = xr[rrow(e0 + TPT + k)];
    }

    #define E(i) ((i) < 0 ? hl[(i) + 5] : ((i) >= TPT ? hr[(i) - TPT] : v[(i)]))

    // ===== stats1 ============================================================
    float s1 = 0.f, ss1 = 0.f;
    {
        float s5 = E(-2) + E(-1) + E(0) + E(1) + E(2);
        #pragma unroll
        for (int o = 0; o < TPT; o++) {
            if (o) s5 += E(o + 2) - E(o - 3);
            float r = v[o] - 0.2f * s5;
            s1 += r;  ss1 += r * r;
        }
    }
    const float thr1 = cluster_threshold(cl, s1, ss1, sm, rank, tid);

    // ===== update1 (registers -> registers) ==================================
    float r[TPT];
    {
        const float thr = thr1;
        float s5  = E(-2) + E(-1) + E(0) + E(1) + E(2);
        float s11 = E(-5) + E(-4) + E(-3) + E(-2) + E(-1) + E(0) +
                    E(1) + E(2) + E(3) + E(4) + E(5);
        #pragma unroll
        for (int o = 0; o < TPT; o++) {
            if (o) {
                s5  += E(o + 2) - E(o - 3);
                s11 += E(o + 5) - E(o - 6);
            }
            float rr = v[o] - 0.2f * s5;
            float f  = (fabsf(rr) > thr) ? F_DAMP : F_KEEP;
            float cc = fmaf(s5, C5, s11 * C11);
            r[o] = fmaf(rr, f, cc);
        }
    }
    #undef E

    // ===== r halos: shuffles + boundary exchange through tiny smem ==========
    float hl2[5], hr2[5];
    #pragma unroll
    for (int k = 0; k < 5; k++) {
        hl2[k] = __shfl_up_sync(FULL, r[11 + k], 1);
        hr2[k] = __shfl_down_sync(FULL, r[k], 1);
    }
    // publish warp-boundary r values
    if (lane == 0) {
        #pragma unroll
        for (int k = 0; k < 5; k++) sm[OFF_AF + w * 5 + k] = r[k];
    }
    if (lane == 31) {
        #pragma unroll
        for (int k = 0; k < 5; k++) sm[OFF_AL + w * 5 + k] = r[11 + k];
    }
    // CTA-boundary: push to peer rank (or local row reflect)
    if (tid == 0) {
        if (rank > 0) {
            float* peer = cl.map_shared_rank(sm, rank - 1);
            #pragma unroll
            for (int k = 0; k < 5; k++) peer[OFF_HCR + k] = r[k];
        } else {
            #pragma unroll
            for (int k = 0; k < 5; k++) sm[OFF_HCL + k] = r[5 - k];  // e[-5+k]=e[5-k]
        }
    }
    if (tid == THREADS - 1) {
        if (rank < CSIZE - 1) {
            float* peer = cl.map_shared_rank(sm, rank + 1);
            #pragma unroll
            for (int k = 0; k < 5; k++) peer[OFF_HCL + k] = r[11 + k];
        } else {
            #pragma unroll
            for (int k = 0; k < 5; k++) sm[OFF_HCR + k] = r[14 - k]; // e[L+k]=e[L-2-k]
        }
    }
    cl.sync();   // halo publishes visible cluster-wide

    if (lane == 0) {
        #pragma unroll
        for (int k = 0; k < 5; k++)
            hl2[k] = (w == 0) ? sm[OFF_HCL + k] : sm[OFF_AL + (w - 1) * 5 + k];
    }
    if (lane == 31) {
        #pragma unroll
        for (int k = 0; k < 5; k++)
            hr2[k] = (w == NW - 1) ? sm[OFF_HCR + k] : sm[OFF_AF + (w + 1) * 5 + k];
    }

    #define E2(i) ((i) < 0 ? hl2[(i) + 5] : ((i) >= TPT ? hr2[(i) - TPT] : r[(i)]))

    // ===== stats2 ============================================================
    float s2 = 0.f, ss2 = 0.f;
    {
        float s5 = E2(-2) + E2(-1) + E2(0) + E2(1) + E2(2);
        #pragma unroll
        for (int o = 0; o < TPT; o++) {
            if (o) s5 += E2(o + 2) - E2(o - 3);
            float rr = r[o] - 0.2f * s5;
            s2 += rr;  ss2 += rr * rr;
        }
    }
    const float thr2 = cluster_threshold(cl, s2, ss2, sm, rank, tid);

    // ===== update2 -> global =================================================
    {
        const float thr = thr2;
        float s5  = E2(-2) + E2(-1) + E2(0) + E2(1) + E2(2);
        float s11 = E2(-5) + E2(-4) + E2(-3) + E2(-2) + E2(-1) + E2(0) +
                    E2(1) + E2(2) + E2(3) + E2(4) + E2(5);
        float4* go = reinterpret_cast<float4*>(out + (size_t)row * ROW_LEN + e0);
        #pragma unroll
        for (int i = 0; i < TPT / 4; i++) {
            float4 o4;
            float* op = reinterpret_cast<float*>(&o4);
            #pragma unroll
            for (int q = 0; q < 4; q++) {
                int o = i * 4 + q;
                if (o) {
                    s5  += E2(o + 2) - E2(o - 3);
                    s11 += E2(o + 5) - E2(o - 6);
                }
                float rr = r[o] - 0.2f * s5;
                float f  = (fabsf(rr) > thr) ? F_DAMP : F_KEEP;
                float cc = fmaf(s5, C5, s11 * C11);
                op[q] = fmaf(rr, f, cc);
            }
            go[i] = o4;
        }
    }
    #undef E2
    // After the thr2 cl.sync no thread touches peer SMEM -> safe exit.
}

extern "C" void kernel_launch(void* const* d_in, const int* in_sizes, int n_in,
                              void* d_out, int out_size)
{
    const float* x = (const float*)d_in[0];
    float* out = (float*)d_out;
    const int rows = in_sizes[0] / ROW_LEN;   // 512

    cudaFuncSetAttribute(fd11_kernel,
                         cudaFuncAttributeMaxDynamicSharedMemorySize, SMEM_BYTES);
    fd11_kernel<<<rows * CSIZE, THREADS, SMEM_BYTES>>>(x, out);
}

// round 12
// speedup vs baseline: 1.2140x; 1.2140x over previous
#include <cuda_runtime.h>
#include <cooperative_groups.h>
#include <math.h>

namespace cg = cooperative_groups;

#define ROW_LEN   65536
#define CSIZE     8
#define SEG       (ROW_LEN / CSIZE)     // 8192 elements per CTA
#define THREADS   256
#define TPT       32                    // thread streams [base, base+32)
#define JOFF      8

#define TREND_SCALING       0.6f
#define DETAIL_PRESERVATION 0.85f
#define SPIKE_THRESHOLD     3.5f
#define SPIKE_DAMPING       0.35f
#define EPS_STD             1e-6f
#define F_KEEP   DETAIL_PRESERVATION                      // 0.85
#define F_DAMP   (DETAIL_PRESERVATION * SPIKE_DAMPING)    // 0.2975
#define C5       ((1.0f - TREND_SCALING) * 0.2f)          // 0.08
#define C11      (TREND_SCALING / 11.0f)

// XOR swizzle: permutes quads within 128B rows by row index; all float4
// LDS/STS at per-lane stride of 32 floats are bank-conflict-free.
__device__ __forceinline__ int SX(int j) { return j ^ ((j >> 3) & 0x1C); }

// smem layout (floats): data cells j in [0, 8224), then scratch
#define OFF_RED     8224                // 17 floats: warp partials + thr
#define OFF_MAIL    8244                // 16 floats: per-rank (s, ss)
#define SMEM_FLOATS 8260
#define SMEM_BYTES  (SMEM_FLOATS * 4)

__device__ __forceinline__ float4 LD4(const float* sm, int j) {
    return *reinterpret_cast<const float4*>(sm + SX(j));
}
__device__ __forceinline__ void ST4(float* sm, int j, float4 v) {
    *reinterpret_cast<float4*>(sm + SX(j)) = v;
}

__global__ void __launch_bounds__(THREADS, 4) __cluster_dims__(CSIZE, 1, 1)
fd12_kernel(const float* __restrict__ x, float* __restrict__ out)
{
    extern __shared__ float sm[];
    float* red  = sm + OFF_RED;
    float* mail = sm + OFF_MAIL;

    cg::cluster_group cl = cg::this_cluster();
    const int rank = (int)cl.block_rank();
    const int row  = blockIdx.x / CSIZE;
    const int tid  = threadIdx.x;
    const size_t gbase = (size_t)row * ROW_LEN + (size_t)rank * SEG;
    const int base = JOFF + tid * TPT;   // smem cell of this thread's element 0

    // ---- stage segment into swizzled smem (coalesced LDG.128 -> STS.128) ----
    {
        const float4* gx = reinterpret_cast<const float4*>(x + gbase);
        #pragma unroll
        for (int g = 0; g < SEG / (THREADS * 4); g++) {     // 8
            int q = g * (THREADS * 4) + tid * 4;
            ST4(sm, JOFF + q, gx[q >> 2]);
        }
    }

    for (int iter = 0; iter < 2; iter++) {
        cl.sync();   // data (stage or iter-0 stores) visible cluster-wide

        // ---- halo cells: 8 left / 8 right (5 meaningful + zero pad) ----
        if (tid < 8) {
            int d = 8 - tid;                 // 8..1 ; cell e[-d]
            float lv = 0.f;
            if (d <= 5) {
                if (rank == 0) {
                    lv = sm[SX(JOFF + d)];                   // reflect -d -> d
                } else {
                    const float* peer = cl.map_shared_rank(sm, rank - 1);
                    lv = peer[SX(JOFF + SEG - d)];
                }
            }
            sm[SX(JOFF - d)] = lv;

            int k = tid;                     // 0..7 ; cell e[SEG+k]
            float rv = 0.f;
            if (k <= 4) {
                if (rank == CSIZE - 1) {
                    rv = sm[SX(JOFF + SEG - 2 - k)];         // reflect L+k -> L-2-k
                } else {
                    const float* peer = cl.map_shared_rank(sm, rank + 1);
                    rv = peer[SX(JOFF + k)];
                }
            }
            sm[SX(JOFF + SEG + k)] = rv;
        }
        __syncthreads();

        // ---- stats stream: sum/sumsq of residual = cur - box5(cur) ----
        float s = 0.f, ss = 0.f;
        {
            float4 p = LD4(sm, base - 4);
            float4 c = LD4(sm, base);
            float t2 = p.z, t3 = p.w;                // e[-2], e[-1]
            float s5 = t2 + t3 + c.x + c.y + c.z;
            #pragma unroll
            for (int k = 0; k < 8; k++) {
                float4 n = LD4(sm, base + 4 * k + 4);
                float r;
                r = c.x - 0.2f * s5; s += r; ss += r * r;
                s5 += c.w - t2;
                r = c.y - 0.2f * s5; s += r; ss += r * r;
                s5 += n.x - t3;
                r = c.z - 0.2f * s5; s += r; ss += r * r;
                s5 += n.y - c.x;
                r = c.w - 0.2f * s5; s += r; ss += r * r;
                s5 += n.z - c.y;
                t2 = c.z; t3 = c.w;
                c = n;
            }
        }

        // ---- block reduce (deterministic order) ----
        const unsigned m = 0xffffffffu;
        #pragma unroll
        for (int off = 16; off; off >>= 1) {
            s  += __shfl_down_sync(m, s,  off);
            ss += __shfl_down_sync(m, ss, off);
        }
        const int wid = tid >> 5, lid = tid & 31;
        if (lid == 0) { red[wid] = s; red[8 + wid] = ss; }
        __syncthreads();

        // ---- PUSH partials into every CTA's mailbox (incl. own) ----
        if (tid == 0) {
            float bs = 0.f, bss = 0.f;
            #pragma unroll
            for (int w = 0; w < 8; w++) { bs += red[w]; bss += red[8 + w]; }
            #pragma unroll
            for (int r2 = 0; r2 < CSIZE; r2++) {
                float* pm = cl.map_shared_rank(sm, r2) + OFF_MAIL;
                pm[2 * rank]     = bs;
                pm[2 * rank + 1] = bss;
            }
        }
        cl.sync();   // pushes visible; all cross-CTA reads complete before stores

        // ---- local mailbox reduce, fixed rank order (identical everywhere) ----
        if (tid == 0) {
            float cs = 0.f, css = 0.f;
            #pragma unroll
            for (int r2 = 0; r2 < CSIZE; r2++) {
                cs  += mail[2 * r2];
                css += mail[2 * r2 + 1];
            }
            const float n = (float)ROW_LEN;
            float var = (css - cs * cs / n) / (n - 1.0f);
            var = fmaxf(var, 0.0f);
            float sc = fmaxf(sqrtf(var), EPS_STD);
            red[16] = sc * SPIKE_THRESHOLD;
        }
        __syncthreads();
        const float thr = red[16];

        // ---- update stream ----
        // iter 0 (in-place): preload overlap values (old), barrier, then stream
        // with reads 2 quads ahead of writes. iter 1: no hazard, all in-stream.
        // NOTE: e[-5] comes from the conflict-free quad LD4(base-8).w — cells
        // base-8..-6 are the zero-padded halo cells. (The scalar sm[SX(base-5)]
        // variant is a 32-way bank conflict: 128B lane stride, same bank.)
        float4 lm  = LD4(sm, base - 8);
        float4 l   = LD4(sm, base - 4);
        float  em5 = lm.w;
        float4 r6, r7;
        if (iter == 0) {
            r6 = LD4(sm, base + 32);
            r7 = LD4(sm, base + 36);
            __syncthreads();   // all cross-thread old-value reads done
        }

        float4 a = LD4(sm, base);         // quad [0,4)
        float4 b = LD4(sm, base + 4);     // quad [4,8)
        float4 qm1 = l;                   // quad [-4,0)
        float  s5  = l.z + l.w + a.x + a.y + a.z;
        float  s11 = em5 + l.x + l.y + l.z + l.w +
                     a.x + a.y + a.z + a.w + b.x + b.y;

        float4* go = reinterpret_cast<float4*>(out + gbase + tid * TPT);

        #pragma unroll
        for (int k = 0; k < 8; k++) {
            float4 n;
            if (iter == 0) n = (k < 6) ? LD4(sm, base + 4 * k + 8)
                                       : ((k == 6) ? r6 : r7);
            else           n = LD4(sm, base + 4 * k + 8);

            float4 o4;
            float r, f, cc;

            r  = a.x - 0.2f * s5;
            f  = (fabsf(r) > thr) ? F_DAMP : F_KEEP;
            cc = fmaf(s5, C5, s11 * C11);
            o4.x = fmaf(r, f, cc);
            s5  += a.w - qm1.z;   s11 += b.z - em5;

            r  = a.y - 0.2f * s5;
            f  = (fabsf(r) > thr) ? F_DAMP : F_KEEP;
            cc = fmaf(s5, C5, s11 * C11);
            o4.y = fmaf(r, f, cc);
            s5  += b.x - qm1.w;   s11 += b.w - qm1.x;

            r  = a.z - 0.2f * s5;
            f  = (fabsf(r) > thr) ? F_DAMP : F_KEEP;
            cc = fmaf(s5, C5, s11 * C11);
            o4.z = fmaf(r, f, cc);
            s5  += b.y - a.x;     s11 += n.x - qm1.y;

            r  = a.w - 0.2f * s5;
            f  = (fabsf(r) > thr) ? F_DAMP : F_KEEP;
            cc = fmaf(s5, C5, s11 * C11);
            o4.w = fmaf(r, f, cc);
            s5  += b.z - a.y;     s11 += n.y - qm1.z;

            if (iter == 0) ST4(sm, base + 4 * k, o4);
            else           go[k] = o4;

            em5 = qm1.w;
            qm1 = a; a = b; b = n;
        }
    }

    // lifetime: no CTA exits while a peer may still touch its SMEM
    cl.sync();
}

extern "C" void kernel_launch(void* const* d_in, const int* in_sizes, int n_in,
                              void* d_out, int out_size)
{
    const float* x = (const float*)d_in[0];
    float* out = (float*)d_out;
    const int rows = in_sizes[0] / ROW_LEN;   // 512

    cudaFuncSetAttribute(fd12_kernel,
                         cudaFuncAttributeMaxDynamicSharedMemorySize, SMEM_BYTES);
    fd12_kernel<<<rows * CSIZE, THREADS, SMEM_BYTES>>>(x, out);
}